// round 1
// baseline (speedup 1.0000x reference)
#include <cuda_runtime.h>
#include <math.h>

#define NLEV 3
#define NBMAX 16
#define MAXB 64
#define NCLS 80

__constant__ float c_stride[NLEV] = {8.f, 16.f, 32.f};
__constant__ float c_anchor[NLEV][3][2] = {
    {{12.f, 16.f}, {19.f, 36.f}, {40.f, 28.f}},
    {{36.f, 75.f}, {76.f, 55.f}, {72.f, 146.f}},
    {{142.f, 110.f}, {192.f, 243.f}, {459.f, 401.f}}
};

// Scratch (no allocations allowed): gathered true boxes per (level, image)
__device__ float4 g_boxes[NLEV][NBMAX][MAXB];  // x1,y1,x2,y2 (precomputed corners)
__device__ float  g_area [NLEV][NBMAX][MAXB];  // w*h
__device__ int    g_count[NLEV][NBMAX];
__device__ double g_acc[3];                    // reg, conf, prob (pre mean-divide)

__global__ void k_init() {
    int t = threadIdx.x;
    if (t < 3) g_acc[t] = 0.0;
    if (t < NLEV * NBMAX) ((int*)g_count)[t] = 0;
}

// Gather positive boxes (label_conf > 0). Order within the set is irrelevant:
// they only feed a max-IoU. Truncation beyond 64 is astronomically improbable.
__global__ void k_gather(const float* __restrict__ label, int HW, int N, int lev) {
    int i = blockIdx.x * blockDim.x + threadIdx.x;  // over N*HW*3 cells, label-flat order
    if (i >= N * HW * 3) return;
    const float* L = label + (size_t)i * 85;
    float conf = L[4];
    if (conf > 0.f) {
        int n = i / (HW * 3);
        int slot = atomicAdd(&g_count[lev][n], 1);
        if (slot < MAXB) {
            float x = L[0], y = L[1], w = L[2], h = L[3];
            g_boxes[lev][n][slot] = make_float4(x - 0.5f * w, y - 0.5f * h,
                                                x + 0.5f * w, y + 0.5f * h);
            g_area[lev][n][slot] = w * h;
        }
    }
}

__device__ __forceinline__ float bce_logits(float x, float t) {
    // max(x,0) - x*t + log1p(exp(-|x|))
    return fmaxf(x, 0.f) - x * t + __logf(1.f + __expf(-fabsf(x)));
}

__global__ void __launch_bounds__(256)
k_loss(const float* __restrict__ feat, const float* __restrict__ label,
       int H, int W, int lev) {
    const int HW = H * W;
    const int n = blockIdx.y;
    const int idx = blockIdx.x * blockDim.x + threadIdx.x;  // a*HW + hw
    const bool active = idx < 3 * HW;

    __shared__ float4 s_box[MAXB];
    __shared__ float  s_area[MAXB];

    int cnt = min(g_count[lev][n], MAXB);
    if (threadIdx.x < cnt) {
        s_box[threadIdx.x]  = g_boxes[lev][n][threadIdx.x];
        s_area[threadIdx.x] = g_area[lev][n][threadIdx.x];
    }
    __syncthreads();

    float r_reg = 0.f, r_conf = 0.f, r_prob = 0.f;

    if (active) {
        const int a  = idx / HW;
        const int hw = idx - a * HW;
        const float gx = (float)(hw % W);
        const float gy = (float)(hw / W);
        const float stride = c_stride[lev];
        const float aw = c_anchor[lev][a][0];
        const float ah = c_anchor[lev][a][1];

        // feature: (N, 255, H, W); channels [a*85 .. a*85+4] for this cell
        const float* fb = feat + ((size_t)(n * 255 + a * 85)) * HW + hw;
        const float rx = fb[0];
        const float ry = fb[(size_t)HW];
        const float rw = fb[(size_t)2 * HW];
        const float rh = fb[(size_t)3 * HW];
        const float rc = fb[(size_t)4 * HW];

        // label: (N, H, W, 3, 85)
        const size_t lb = ((size_t)(n * HW + hw) * 3 + a) * 85;
        const float lc = __ldg(label + lb + 4);

        // predicted box (absolute xywh -> corners)
        const float px = (__fdividef(1.f, 1.f + __expf(-rx)) + gx) * stride;
        const float py = (__fdividef(1.f, 1.f + __expf(-ry)) + gy) * stride;
        const float pw = __expf(rw) * aw;
        const float ph = __expf(rh) * ah;
        const float px1 = px - 0.5f * pw, py1 = py - 0.5f * ph;
        const float px2 = px + 0.5f * pw, py2 = py + 0.5f * ph;
        const float pa = pw * ph;

        // ignore_mask = (max_iou < 0.5); iou<0.5 <=> 2*inter < max(union,1e-9)
        bool ignore = true;
        #pragma unroll 4
        for (int b = 0; b < cnt; b++) {
            float4 t = s_box[b];
            float iw = fminf(px2, t.z) - fmaxf(px1, t.x);
            float ih = fminf(py2, t.w) - fmaxf(py1, t.y);
            iw = fmaxf(iw, 0.f);
            ih = fmaxf(ih, 0.f);
            float inter = iw * ih;
            float uni = fmaxf(pa + s_area[b] - inter, 1e-9f);
            if (2.f * inter >= uni) ignore = false;
        }

        const float bc = bce_logits(rc, lc);
        r_conf = (lc > 0.f) ? bc : (ignore ? bc : 0.f);

        if (lc > 0.f) {  // rare positive path (~0.08% of cells)
            const float lx = __ldg(label + lb + 0);
            const float ly = __ldg(label + lb + 1);
            const float lw = __ldg(label + lb + 2);
            const float lh = __ldg(label + lb + 3);
            const float scale = 2.f - lw * lh * (1.f / (416.f * 416.f));
            const float inv_s = __fdividef(1.f, stride);
            const float ox = lx * inv_s - gx;
            const float oy = ly * inv_s - gy;
            float xy = bce_logits(rx, ox) + bce_logits(ry, oy);
            const float wx = __logf(__fdividef(lw, aw) + 1e-7f);
            const float wy = __logf(__fdividef(lh, ah) + 1e-7f);
            const float dwx = rw - wx, dwy = rh - wy;
            const float wh = 0.5f * (dwx * dwx + dwy * dwy);
            r_reg = scale * (xy + wh);

            float ps = 0.f;
            #pragma unroll 4
            for (int c = 0; c < NCLS; c++) {
                float rp = fb[(size_t)(5 + c) * HW];
                float lp = __ldg(label + lb + 5 + c);
                ps += bce_logits(rp, lp);
            }
            r_prob = ps;
        }
    }

    // block reduction (warp shuffle, then cross-warp), one double atomic per block
    #pragma unroll
    for (int o = 16; o; o >>= 1) {
        r_reg  += __shfl_xor_sync(0xffffffffu, r_reg,  o);
        r_conf += __shfl_xor_sync(0xffffffffu, r_conf, o);
        r_prob += __shfl_xor_sync(0xffffffffu, r_prob, o);
    }
    __shared__ float s_r[8], s_c[8], s_p[8];
    const int warp = threadIdx.x >> 5, lane = threadIdx.x & 31;
    if (lane == 0) { s_r[warp] = r_reg; s_c[warp] = r_conf; s_p[warp] = r_prob; }
    __syncthreads();
    if (threadIdx.x == 0) {
        float R = 0.f, C = 0.f, P = 0.f;
        const int nw = blockDim.x >> 5;
        for (int w = 0; w < nw; w++) { R += s_r[w]; C += s_c[w]; P += s_p[w]; }
        atomicAdd(&g_acc[0], (double)R);
        atomicAdd(&g_acc[1], (double)C);
        atomicAdd(&g_acc[2], (double)P);
    }
}

__global__ void k_final(float* out, float invN) {
    if (threadIdx.x < 3) out[threadIdx.x] = (float)(g_acc[threadIdx.x] * (double)invN);
}

extern "C" void kernel_launch(void* const* d_in, const int* in_sizes, int n_in,
                              void* d_out, int out_size) {
    const float* pred[NLEV] = {(const float*)d_in[0], (const float*)d_in[1], (const float*)d_in[2]};
    const float* lab [NLEV] = {(const float*)d_in[3], (const float*)d_in[4], (const float*)d_in[5]};
    const int Hs[NLEV] = {52, 26, 13};

    int N = in_sizes[0] / (255 * 52 * 52);
    if (N > NBMAX) N = NBMAX;

    k_init<<<1, 64>>>();

    for (int l = 0; l < NLEV; l++) {
        int HW = Hs[l] * Hs[l];
        int total = N * HW * 3;
        k_gather<<<(total + 255) / 256, 256>>>(lab[l], HW, N, l);
    }

    for (int l = 0; l < NLEV; l++) {
        int H = Hs[l], W = Hs[l];
        int HW = H * W;
        dim3 grid((3 * HW + 255) / 256, N);
        k_loss<<<grid, 256>>>(pred[l], lab[l], H, W, l);
    }

    k_final<<<1, 32>>>((float*)d_out, 1.0f / (float)N);
}

// round 2
// speedup vs baseline: 1.9599x; 1.9599x over previous
#include <cuda_runtime.h>
#include <math.h>

#define NLEV 3
#define NBMAX 16
#define MAXB 64
#define NCLS 80
// per-image cells per level: 3*52*52=8112, 3*26*26=2028, 3*13*13=507, total 10647
#define CPI0 8112
#define CPI1 2028
#define CPI2 507
#define CPI_ALL 10647
#define MASK_WORDS ((NBMAX * CPI_ALL + 31) / 32 + 8)   // ~5332
// loss blocks per image: ceil(8112/256)=32, ceil(2028/256)=8, ceil(507/256)=2
#define LB0 32
#define LB1 8
#define LB2 2
#define LBPI (LB0 + LB1 + LB2)   // 42

__constant__ float c_stride[NLEV] = {8.f, 16.f, 32.f};
__constant__ float c_anchor[NLEV][3][2] = {
    {{12.f, 16.f}, {19.f, 36.f}, {40.f, 28.f}},
    {{36.f, 75.f}, {76.f, 55.f}, {72.f, 146.f}},
    {{142.f, 110.f}, {192.f, 243.f}, {459.f, 401.f}}
};

// Scratch (no allocations allowed)
__device__ float4   g_boxes[NLEV][NBMAX][MAXB];   // x1,y1,x2,y2 corners
__device__ float    g_area [NLEV][NBMAX][MAXB];   // w*h
__device__ int      g_count[NLEV][NBMAX];
__device__ unsigned g_mask[MASK_WORDS];           // positivity bit per cell (global cell idx)
__device__ double   g_acc[3];                     // reg, conf, prob sums
__device__ unsigned g_done;

__global__ void k_init() {
    int t = threadIdx.x;
    for (int i = t; i < MASK_WORDS; i += 256) g_mask[i] = 0u;
    if (t < 3) g_acc[t] = 0.0;
    if (t < NLEV * NBMAX) ((int*)g_count)[t] = 0;
    if (t == 0) g_done = 0u;
}

// Fused 3-level gather of positive boxes + positivity bitmask.
// Global cell index i is: level offset + label-flat index j, j = (n*HW + hw)*3 + a.
__global__ void __launch_bounds__(256)
k_gather(const float* __restrict__ lab0, const float* __restrict__ lab1,
         const float* __restrict__ lab2, int N) {
    const int c0 = N * CPI0, c1 = N * CPI1;
    const int total = N * CPI_ALL;
    int i = blockIdx.x * blockDim.x + threadIdx.x;
    if (i >= total) return;

    int lev, j, HW;
    const float* L;
    if (i < c0)            { lev = 0; j = i;            HW = 2704; L = lab0; }
    else if (i < c0 + c1)  { lev = 1; j = i - c0;       HW = 676;  L = lab1; }
    else                   { lev = 2; j = i - c0 - c1;  HW = 169;  L = lab2; }

    const float conf = __ldg(L + (size_t)j * 85 + 4);
    if (conf > 0.f) {
        atomicOr(&g_mask[i >> 5], 1u << (i & 31));
        int n = j / (HW * 3);
        int slot = atomicAdd(&g_count[lev][n], 1);
        if (slot < MAXB) {
            const float* p = L + (size_t)j * 85;
            float x = p[0], y = p[1], w = p[2], h = p[3];
            g_boxes[lev][n][slot] = make_float4(x - 0.5f * w, y - 0.5f * h,
                                                x + 0.5f * w, y + 0.5f * h);
            g_area[lev][n][slot] = w * h;
        }
    }
}

__device__ __forceinline__ float bce_logits(float x, float t) {
    return fmaxf(x, 0.f) - x * t + __logf(1.f + __expf(-fabsf(x)));
}

// Fused 3-level loss + finalize-in-last-block.
__global__ void __launch_bounds__(256)
k_loss(const float* __restrict__ f0, const float* __restrict__ f1,
       const float* __restrict__ f2,
       const float* __restrict__ lab0, const float* __restrict__ lab1,
       const float* __restrict__ lab2,
       int N, float* __restrict__ out) {
    // decode (n, level, chunk) from linear blockIdx
    const int b = blockIdx.x;
    const int n = b / LBPI;
    const int r = b - n * LBPI;
    int lev, chunk, H;
    const float* feat; const float* label; int levoff;
    const int c0 = N * CPI0, c1 = N * CPI1;
    if (r < LB0)            { lev = 0; chunk = r;        H = 52; feat = f0; label = lab0; levoff = 0; }
    else if (r < LB0 + LB1) { lev = 1; chunk = r - LB0;  H = 26; feat = f1; label = lab1; levoff = c0; }
    else                    { lev = 2; chunk = r - LB0 - LB1; H = 13; feat = f2; label = lab2; levoff = c0 + c1; }
    const int W = H, HW = H * W;

    __shared__ float4 s_box[MAXB];
    __shared__ float  s_area[MAXB];
    const int cnt = min(g_count[lev][n], MAXB);
    if (threadIdx.x < cnt) {
        s_box[threadIdx.x]  = g_boxes[lev][n][threadIdx.x];
        s_area[threadIdx.x] = g_area[lev][n][threadIdx.x];
    }
    __syncthreads();

    const int idx = chunk * 256 + threadIdx.x;   // a*HW + hw, feature-friendly order
    float r_reg = 0.f, r_conf = 0.f, r_prob = 0.f;

    if (idx < 3 * HW) {
        const int a  = idx / HW;
        const int hw = idx - a * HW;
        const float gx = (float)(hw % W);
        const float gy = (float)(hw / W);
        const float stride = c_stride[lev];
        const float aw = c_anchor[lev][a][0];
        const float ah = c_anchor[lev][a][1];

        const float* fb = feat + ((size_t)(n * 255 + a * 85)) * HW + hw;
        const float rx = fb[0];
        const float ry = fb[(size_t)HW];
        const float rw = fb[(size_t)2 * HW];
        const float rh = fb[(size_t)3 * HW];
        const float rc = fb[(size_t)4 * HW];

        // positivity from bitmask (label conf is exactly 0/1)
        const int cell = levoff + (n * HW + hw) * 3 + a;
        const bool pos = (g_mask[cell >> 5] >> (cell & 31)) & 1u;

        // predicted box corners
        const float px = (__fdividef(1.f, 1.f + __expf(-rx)) + gx) * stride;
        const float py = (__fdividef(1.f, 1.f + __expf(-ry)) + gy) * stride;
        const float pw = __expf(rw) * aw;
        const float ph = __expf(rh) * ah;
        const float px1 = px - 0.5f * pw, py1 = py - 0.5f * ph;
        const float px2 = px + 0.5f * pw, py2 = py + 0.5f * ph;
        const float pa = pw * ph;

        // ignore = (max_iou < 0.5);  iou<0.5 <=> 2*inter < max(union,1e-9)
        bool ignore = true;
        #pragma unroll 4
        for (int k = 0; k < cnt; k++) {
            float4 t = s_box[k];
            float iw = fmaxf(fminf(px2, t.z) - fmaxf(px1, t.x), 0.f);
            float ih = fmaxf(fminf(py2, t.w) - fmaxf(py1, t.y), 0.f);
            float inter = iw * ih;
            float uni = fmaxf(pa + s_area[k] - inter, 1e-9f);
            if (2.f * inter >= uni) ignore = false;
        }

        const float lc = pos ? 1.f : 0.f;
        const float bc = bce_logits(rc, lc);
        r_conf = pos ? bc : (ignore ? bc : 0.f);

        if (pos) {   // rare path (~0.08% of cells): read the label tensor
            const size_t lb = ((size_t)(n * HW + hw) * 3 + a) * 85;
            const float lx = __ldg(label + lb + 0);
            const float ly = __ldg(label + lb + 1);
            const float lw = __ldg(label + lb + 2);
            const float lh = __ldg(label + lb + 3);
            const float scale = 2.f - lw * lh * (1.f / (416.f * 416.f));
            const float inv_s = __fdividef(1.f, stride);
            const float ox = lx * inv_s - gx;
            const float oy = ly * inv_s - gy;
            float xy = bce_logits(rx, ox) + bce_logits(ry, oy);
            const float wx = __logf(__fdividef(lw, aw) + 1e-7f);
            const float wy = __logf(__fdividef(lh, ah) + 1e-7f);
            const float dwx = rw - wx, dwy = rh - wy;
            r_reg = scale * (xy + 0.5f * (dwx * dwx + dwy * dwy));

            float ps = 0.f;
            #pragma unroll 4
            for (int c = 0; c < NCLS; c++) {
                float rp = fb[(size_t)(5 + c) * HW];
                float lp = __ldg(label + lb + 5 + c);
                ps += bce_logits(rp, lp);
            }
            r_prob = ps;
        }
    }

    // block reduction
    #pragma unroll
    for (int o = 16; o; o >>= 1) {
        r_reg  += __shfl_xor_sync(0xffffffffu, r_reg,  o);
        r_conf += __shfl_xor_sync(0xffffffffu, r_conf, o);
        r_prob += __shfl_xor_sync(0xffffffffu, r_prob, o);
    }
    __shared__ float s_r[8], s_c[8], s_p[8];
    const int warp = threadIdx.x >> 5, lane = threadIdx.x & 31;
    if (lane == 0) { s_r[warp] = r_reg; s_c[warp] = r_conf; s_p[warp] = r_prob; }
    __syncthreads();

    if (threadIdx.x == 0) {
        float R = 0.f, C = 0.f, P = 0.f;
        #pragma unroll
        for (int w = 0; w < 8; w++) { R += s_r[w]; C += s_c[w]; P += s_p[w]; }
        atomicAdd(&g_acc[0], (double)R);
        atomicAdd(&g_acc[1], (double)C);
        atomicAdd(&g_acc[2], (double)P);

        __threadfence();
        unsigned t = atomicAdd(&g_done, 1u);
        if (t == (unsigned)gridDim.x - 1u) {   // last block: finalize
            double invN = 1.0 / (double)N;
            // read via atomic to bypass any stale caching
            double v0 = atomicAdd(&g_acc[0], 0.0);
            double v1 = atomicAdd(&g_acc[1], 0.0);
            double v2 = atomicAdd(&g_acc[2], 0.0);
            out[0] = (float)(v0 * invN);
            out[1] = (float)(v1 * invN);
            out[2] = (float)(v2 * invN);
        }
    }
}

extern "C" void kernel_launch(void* const* d_in, const int* in_sizes, int n_in,
                              void* d_out, int out_size) {
    const float* f0 = (const float*)d_in[0];
    const float* f1 = (const float*)d_in[1];
    const float* f2 = (const float*)d_in[2];
    const float* l0 = (const float*)d_in[3];
    const float* l1 = (const float*)d_in[4];
    const float* l2 = (const float*)d_in[5];

    int N = in_sizes[0] / (255 * 52 * 52);
    if (N > NBMAX) N = NBMAX;

    k_init<<<1, 256>>>();

    int gtotal = N * CPI_ALL;
    k_gather<<<(gtotal + 255) / 256, 256>>>(l0, l1, l2, N);

    k_loss<<<N * LBPI, 256>>>(f0, f1, f2, l0, l1, l2, N, (float*)d_out);
}